// round 16
// baseline (speedup 1.0000x reference)
#include <cuda_runtime.h>

typedef unsigned long long u64;

#define B_ 4096
#define T_ 128
#define I_ 16
#define H_ 64
#define NB 4      // batches per CTA
#define NTR 256   // 8 warps; thread = (unit-pair p = w*4+(lane&3), k-octant o = lane>>2)

// ---- packed f32x2 helpers (sm_100+; ptxas never emits these from C++) ----
__device__ __forceinline__ void upk2(u64 v, float& lo, float& hi) {
    asm("mov.b64 {%0,%1}, %2;" : "=f"(lo), "=f"(hi) : "l"(v));
}
__device__ __forceinline__ u64 fma2(u64 a, u64 b, u64 c) {
    u64 d; asm("fma.rn.f32x2 %0, %1, %2, %3;" : "=l"(d) : "l"(a), "l"(b), "l"(c)); return d;
}
__device__ __forceinline__ u64 mul2(u64 a, u64 b) {
    u64 d; asm("mul.rn.f32x2 %0, %1, %2;" : "=l"(d) : "l"(a), "l"(b)); return d;
}
__device__ __forceinline__ u64 add2(u64 a, u64 b) {
    u64 d; asm("add.rn.f32x2 %0, %1, %2;" : "=l"(d) : "l"(a), "l"(b)); return d;
}
__device__ __forceinline__ float red2(u64 v) { float lo, hi; upk2(v, lo, hi); return lo + hi; }
__device__ __forceinline__ u64 shfl64(u64 v, int m) {
    return __shfl_xor_sync(0xFFFFFFFFu, v, m);
}

// exp-based activations (~1e-6/step; tanh.approx's 2^-11 would compound over T=128)
__device__ __forceinline__ float sigmoidf_(float a) { return __fdividef(1.0f, 1.0f + __expf(-a)); }
__device__ __forceinline__ float tanhf_(float a)    { return __fdividef(2.0f, 1.0f + __expf(-2.0f * a)) - 1.0f; }

__global__ void __launch_bounds__(NTR, 2) gru_fused_kernel(
    const float* __restrict__ x,     // [B, T, I]
    const float* __restrict__ w_ih,  // [3H, I]
    const float* __restrict__ w_hh,  // [3H, H]
    const float* __restrict__ b_ih,  // [3H]
    const float* __restrict__ b_hh,  // [3H]
    const float* __restrict__ fc_w,  // [1, H]
    const float* __restrict__ fc_b,  // [1]
    float* __restrict__ out)         // [B]
{
    __shared__ __align__(16) float sx[NB][T_][I_];   // 32 KB: x for 4 batches
    __shared__ __align__(16) float hb[2][NB][H_];    // 2 KB: double-buffered h

    const int tid  = threadIdx.x;
    const int lane = tid & 31;
    const int w    = tid >> 5;            // warp 0..7
    const int p    = w * 4 + (lane & 3);  // unit pair 0..31 -> units (p, p+32)
    const int o    = lane >> 2;           // k-octant 0..7: k in [8o, 8o+8)
    const int mu   = o >> 2;              // unit this lane finishes (0->p, 1->p+32)
    const int bf   = o & 3;               // batch this lane finishes
    const int jf   = mu ? (p + 32) : p;   // kept unit
    const int jS   = mu ? p : (p + 32);   // sent unit
    const int bBase = blockIdx.x * NB;

    // ---- register-resident weights, XOR-slotted: K = kept unit jf, S = sent unit jS ----
    u64 whrK[4], whzK[4], whnK[4], whrS[4], whzS[4], whnS[4];
    {
        const u64* a0 = reinterpret_cast<const u64*>(w_hh + (jf          ) * H_ + o * 8);
        const u64* a1 = reinterpret_cast<const u64*>(w_hh + (jf +     H_ ) * H_ + o * 8);
        const u64* a2 = reinterpret_cast<const u64*>(w_hh + (jf + 2 * H_ ) * H_ + o * 8);
        const u64* a3 = reinterpret_cast<const u64*>(w_hh + (jS          ) * H_ + o * 8);
        const u64* a4 = reinterpret_cast<const u64*>(w_hh + (jS +     H_ ) * H_ + o * 8);
        const u64* a5 = reinterpret_cast<const u64*>(w_hh + (jS + 2 * H_ ) * H_ + o * 8);
        #pragma unroll
        for (int k = 0; k < 4; k++) {
            whrK[k] = a0[k]; whzK[k] = a1[k]; whnK[k] = a2[k];
            whrS[k] = a3[k]; whzS[k] = a4[k]; whnS[k] = a5[k];
        }
    }
    const u64 wirK = *reinterpret_cast<const u64*>(w_ih + (jf          ) * I_ + o * 2);
    const u64 wizK = *reinterpret_cast<const u64*>(w_ih + (jf +     H_ ) * I_ + o * 2);
    const u64 winK = *reinterpret_cast<const u64*>(w_ih + (jf + 2 * H_ ) * I_ + o * 2);
    const u64 wirS = *reinterpret_cast<const u64*>(w_ih + (jS          ) * I_ + o * 2);
    const u64 wizS = *reinterpret_cast<const u64*>(w_ih + (jS +     H_ ) * I_ + o * 2);
    const u64 winS = *reinterpret_cast<const u64*>(w_ih + (jS + 2 * H_ ) * I_ + o * 2);

    // biases for this lane's finishing (bf, jf)
    const float br  = b_ih[jf]           + b_hh[jf];
    const float bz  = b_ih[jf + H_]      + b_hh[jf + H_];
    const float bnx = b_ih[jf + 2 * H_];
    const float bnh = b_hh[jf + 2 * H_];

    // per-lane XOR-ordered batch offsets (slot i -> batch bf^i)
    int hoff[NB], xoff[NB];
    #pragma unroll
    for (int i = 0; i < NB; i++) {
        hoff[i] = (bf ^ i) * H_ + o * 8;
        xoff[i] = (bf ^ i) * (T_ * I_) + o * 2;
    }

    // ---- preload x for NB batches (coalesced, 32 KB) ----
    {
        const u64* gx = reinterpret_cast<const u64*>(x + (size_t)bBase * (T_ * I_));
        u64* sxu = reinterpret_cast<u64*>(sx);
        #pragma unroll 4
        for (int i = tid; i < NB * T_ * I_ / 2; i += NTR) sxu[i] = gx[i];
    }
    (&hb[0][0][0])[tid] = 0.0f;          // NB*H_ == NTR: zero first read buffer
    __syncthreads();

    const float* hs = &hb[0][0][0];      // read buffer
    float*       hd = &hb[1][0][0];      // write buffer
    const float* xbase = &sx[0][0][0];
    float hold = 0.0f;                   // register-carried h for (bf, jf)

    #pragma unroll 1
    for (int t = 0; t < T_; t++) {
        // Packed reduction end-to-end: slot order (0,2)->mid[0], (1,3)->mid[1];
        // xor8 folded immediately to cap live registers.
        u64 mid[2][4];

        #pragma unroll
        for (int half = 0; half < 2; half++) {
            u64 acc[2][4];               // after xor16: [g][r,z,nx,nh] as f32x2
            #pragma unroll
            for (int g = 0; g < 2; g++) {
                const int i = half + 2 * g;          // slots: half=0 -> 0,2 ; half=1 -> 1,3
                const ulonglong2* hp = reinterpret_cast<const ulonglong2*>(hs + hoff[i]);
                ulonglong2 v0 = hp[0], v1 = hp[1];
                const u64 xv = *reinterpret_cast<const u64*>(xbase + xoff[i]);

                u64 arK = mul2(wirK, xv), azK = mul2(wizK, xv), axK = mul2(winK, xv);
                u64 arS = mul2(wirS, xv), azS = mul2(wizS, xv), axS = mul2(winS, xv);
                u64 ahK = mul2(whnK[0], v0.x), ahS = mul2(whnS[0], v0.x);
                arK = fma2(whrK[0], v0.x, arK); azK = fma2(whzK[0], v0.x, azK);
                arS = fma2(whrS[0], v0.x, arS); azS = fma2(whzS[0], v0.x, azS);
                arK = fma2(whrK[1], v0.y, arK); azK = fma2(whzK[1], v0.y, azK); ahK = fma2(whnK[1], v0.y, ahK);
                arS = fma2(whrS[1], v0.y, arS); azS = fma2(whzS[1], v0.y, azS); ahS = fma2(whnS[1], v0.y, ahS);
                arK = fma2(whrK[2], v1.x, arK); azK = fma2(whzK[2], v1.x, azK); ahK = fma2(whnK[2], v1.x, ahK);
                arS = fma2(whrS[2], v1.x, arS); azS = fma2(whzS[2], v1.x, azS); ahS = fma2(whnS[2], v1.x, ahS);
                arK = fma2(whrK[3], v1.y, arK); azK = fma2(whzK[3], v1.y, azK); ahK = fma2(whnK[3], v1.y, ahK);
                arS = fma2(whrS[3], v1.y, arS); azS = fma2(whzS[3], v1.y, azS); ahS = fma2(whnS[3], v1.y, ahS);

                // unit exchange (xor16) on packed pairs: partner's S-slot is MY unit jf
                acc[g][0] = add2(arK, shfl64(arS, 16));
                acc[g][1] = add2(azK, shfl64(azS, 16));
                acc[g][2] = add2(axK, shfl64(axS, 16));
                acc[g][3] = add2(ahK, shfl64(ahS, 16));
            }
            // batch-scatter xor8 (bit1), folded: partner's g=1 slot is my batch group
            #pragma unroll
            for (int k = 0; k < 4; k++)
                mid[half][k] = add2(acc[0][k], shfl64(acc[1][k], 8));
        }

        // batch-scatter xor4 (bit0) + single intra-pair reduction at the end
        const float fr  = red2(add2(mid[0][0], shfl64(mid[1][0], 4)));
        const float fz  = red2(add2(mid[0][1], shfl64(mid[1][1], 4)));
        const float fnx = red2(add2(mid[0][2], shfl64(mid[1][2], 4)));
        const float fnh = red2(add2(mid[0][3], shfl64(mid[1][3], 4)));

        // ---- finish (bf, jf): activations + state update; hold is register-carried ----
        const float r = sigmoidf_(fr + br);
        const float z = sigmoidf_(fz + bz);
        const float n = tanhf_(fnx + bnx + r * (fnh + bnh));
        hold = n + z * (hold - n);               // (1-z)*n + z*h
        hd[bf * H_ + jf] = hold;
        __syncthreads();                         // one barrier per step

        const float* tp = hs; hs = hd; hd = const_cast<float*>(tp);
        xbase += I_;
    }

    // ---- head: warp w (0..3) reduces batch w; final h is in hs (T even) ----
    if (w < NB) {
        float v = hs[w * H_ + lane] * fc_w[lane] + hs[w * H_ + lane + 32] * fc_w[lane + 32];
        #pragma unroll
        for (int off = 16; off > 0; off >>= 1) v += __shfl_xor_sync(0xFFFFFFFFu, v, off);
        if (lane == 0) out[bBase + w] = v + fc_b[0];
    }
}

extern "C" void kernel_launch(void* const* d_in, const int* in_sizes, int n_in,
                              void* d_out, int out_size) {
    const float* x    = (const float*)d_in[0];
    const float* w_ih = (const float*)d_in[1];
    const float* w_hh = (const float*)d_in[2];
    const float* b_ih = (const float*)d_in[3];
    const float* b_hh = (const float*)d_in[4];
    const float* fc_w = (const float*)d_in[5];
    const float* fc_b = (const float*)d_in[6];
    float* out = (float*)d_out;

    gru_fused_kernel<<<B_ / NB, NTR>>>(x, w_ih, w_hh, b_ih, b_hh, fc_w, fc_b, out);
}